// round 9
// baseline (speedup 1.0000x reference)
#include <cuda_runtime.h>
#include <math.h>
#include <stdint.h>

// Problem constants
#define B_   64
#define D_   2048
#define N_   16384
#define TINV 20.0f          // 1 / TEMP

#define NBLK_ 128           // CTAs; each handles 128 feature rows
#define NKS   64            // k-stages (2048 / 32)
#define STG   4             // cp.async pipeline depth
#define NTHR  256           // 8 warps

// smem layout (bytes). A tile: 128 x 36 floats = 18432 B; B: 64 x 36 = 9216 B.
#define ASTR  36
#define SM_INVN   0                      // 64 floats
#define SM_HP     256                    // 4 x 64 float4 = 4096 B
#define SM_STAGE  4608
#define STGB      27648
#define BOFF      18432
#define SM_L      SM_STAGE               // alias: logits 128 x 65 fp32 (33280 B)
#define SMEM_TOTAL (SM_STAGE + STG * STGB)   // 115200 B

__device__ float4 g_part[B_ * NBLK_];

__device__ __forceinline__ uint32_t smem_u32(const void* p) {
    uint32_t a;
    asm("{ .reg .u64 t; cvta.to.shared.u64 t, %1; cvt.u32.u64 %0, t; }" : "=r"(a) : "l"(p));
    return a;
}
#define CP16(dst, src) \
    asm volatile("cp.async.cg.shared.global [%0], [%1], 16;" :: "r"(dst), "l"(src) : "memory")
#define CP_COMMIT()  asm volatile("cp.async.commit_group;" ::: "memory")
#define CP_WAIT3()   asm volatile("cp.async.wait_group 3;" ::: "memory")

// ---------------------------------------------------------------------------
// Kernel 1 (main): norms from smem B tiles + tf32 mma GEMM + CE partials.
// Warp w: mq=w>>1 owns feat rows 32*mq..+31 (two m16 tiles); nq=w&1 owns
// batch cols 32*nq..+31 (four n8 tiles).
// ---------------------------------------------------------------------------
__global__ void __launch_bounds__(NTHR, 1)
fused_kernel(const float* __restrict__ x, const float* __restrict__ feat,
             const float* __restrict__ targets)
{
    extern __shared__ char smem[];
    const uint32_t sb = smem_u32(smem);
    const int tid  = threadIdx.x;
    const int wid  = tid >> 5;
    const int lane = tid & 31;
    const int gid  = lane >> 2;        // fragment row group 0..7
    const int tig  = lane & 3;         // thread-in-group 0..3
    const int mq   = wid >> 1;         // 4 m-quarters
    const int nq   = wid & 1;          // 2 n-halves
    const int m0   = 32 * mq;
    const int nc0  = 32 * nq;
    const int n0   = blockIdx.x * 128; // feature-row tile base

    // cp.async one k-stage (32 floats per row) into buffer s
    const float* fbase = feat + (size_t)n0 * D_;
    auto load_stage = [&](int ks, int s) {
        const uint32_t abase = sb + SM_STAGE + s * STGB;
#pragma unroll
        for (int i = 0; i < 4; i++) {            // A: 1024 16B chunks
            int id  = tid + NTHR * i;
            int row = id >> 3, c = id & 7;
            CP16(abase + row * (ASTR * 4) + c * 16,
                 fbase + (size_t)row * D_ + ks * 32 + 4 * c);
        }
        const uint32_t bbase = abase + BOFF;
#pragma unroll
        for (int i = 0; i < 2; i++) {            // B: 512 16B chunks
            int id  = tid + NTHR * i;
            int row = id >> 3, c = id & 7;
            CP16(bbase + row * (ASTR * 4) + c * 16,
                 x + (size_t)row * D_ + ks * 32 + 4 * c);
        }
    };

    float acc[2][4][4];
#pragma unroll
    for (int mt = 0; mt < 2; mt++)
#pragma unroll
        for (int nt = 0; nt < 4; nt++)
#pragma unroll
            for (int c = 0; c < 4; c++) acc[mt][nt][c] = 0.f;

    // per-thread norm accumulation mapping: row nr, 8 k's per stage
    const int nr = tid >> 2;
    const int nk = (tid & 3) * 8;
    float nsq = 0.f;

    // prologue
#pragma unroll
    for (int s = 0; s < STG - 1; s++) { load_stage(s, s); CP_COMMIT(); }

    for (int j = 0; j < NKS; j++) {
        if (j + STG - 1 < NKS) load_stage(j + STG - 1, (j + STG - 1) & 3);
        CP_COMMIT();             // uniform group count (empty at tail)
        CP_WAIT3();              // <=3 pending => stage j resident
        __syncthreads();

        const float*    Bf = (const float*)(smem + SM_STAGE + (j & 3) * STGB + BOFF);
        const uint32_t* As = (const uint32_t*)(smem + SM_STAGE + (j & 3) * STGB);
        const uint32_t* Bs = (const uint32_t*)Bf;

        // norm: sum of squares of x tile (each CTA streams all of x anyway)
        {
            float4 q0 = *(const float4*)(Bf + nr * ASTR + nk);
            float4 q1 = *(const float4*)(Bf + nr * ASTR + nk + 4);
            nsq += q0.x * q0.x + q0.y * q0.y + q0.z * q0.z + q0.w * q0.w
                 + q1.x * q1.x + q1.y * q1.y + q1.z * q1.z + q1.w * q1.w;
        }

#pragma unroll
        for (int kk = 0; kk < 32; kk += 8) {
            uint32_t a[2][4];
#pragma unroll
            for (int mt = 0; mt < 2; mt++) {
                int r = m0 + 16 * mt + gid;
                a[mt][0] = As[r * ASTR + kk + tig];
                a[mt][1] = As[(r + 8) * ASTR + kk + tig];
                a[mt][2] = As[r * ASTR + kk + tig + 4];
                a[mt][3] = As[(r + 8) * ASTR + kk + tig + 4];
            }
            uint32_t b[4][2];
#pragma unroll
            for (int nt = 0; nt < 4; nt++) {
                int n = nc0 + 8 * nt + gid;
                b[nt][0] = Bs[n * ASTR + kk + tig];
                b[nt][1] = Bs[n * ASTR + kk + tig + 4];
            }
#pragma unroll
            for (int mt = 0; mt < 2; mt++)
#pragma unroll
                for (int nt = 0; nt < 4; nt++)
                    asm volatile(
                        "mma.sync.aligned.m16n8k8.row.col.f32.tf32.tf32.f32 "
                        "{%0,%1,%2,%3}, {%4,%5,%6,%7}, {%8,%9}, {%0,%1,%2,%3};"
                        : "+f"(acc[mt][nt][0]), "+f"(acc[mt][nt][1]),
                          "+f"(acc[mt][nt][2]), "+f"(acc[mt][nt][3])
                        : "r"(a[mt][0]), "r"(a[mt][1]), "r"(a[mt][2]), "r"(a[mt][3]),
                          "r"(b[nt][0]), "r"(b[nt][1]));
        }
        __syncthreads();         // buffer j&3 reused by load at iter j+1
    }

    // ---- finalize inverse norms (quad covers all 32 k of each stage) ----
    nsq += __shfl_xor_sync(0xffffffffu, nsq, 1);
    nsq += __shfl_xor_sync(0xffffffffu, nsq, 2);
    float* invn = (float*)(smem + SM_INVN);
    if ((tid & 3) == 0) invn[nr] = rsqrtf(nsq);
    __syncthreads();

    // ---- scatter logits to smem transposed (stride 65), scaled ----
    float* sl = (float*)(smem + SM_L);
#pragma unroll
    for (int mt = 0; mt < 2; mt++)
#pragma unroll
        for (int nt = 0; nt < 4; nt++)
#pragma unroll
            for (int c = 0; c < 4; c++) {
                int row = m0 + 16 * mt + gid + 8 * (c >> 1);   // feature 0..127
                int col = nc0 + 8 * nt + 2 * tig + (c & 1);    // batch  0..63
                sl[row * 65 + col] = acc[mt][nt][c] * invn[col] * TINV;
            }
    __syncthreads();

    // ---- per-batch partials: thread (m, h) covers feature rows 32h..32h+31 ----
    {
        const int m = tid & 63;
        const int h = tid >> 6;
        const int f0 = 32 * h;
        float mx = -3.4e38f;
#pragma unroll 8
        for (int f = 0; f < 32; f++) mx = fmaxf(mx, sl[(f0 + f) * 65 + m]);
        float se = 0.f, W = 0.f, Zt = 0.f;
        const float* tr = targets + (size_t)m * N_ + n0 + f0;
        for (int f = 0; f < 32; f += 4) {
            float4 t4 = *(const float4*)(tr + f);
            float l0 = sl[(f0 + f + 0) * 65 + m];
            float l1 = sl[(f0 + f + 1) * 65 + m];
            float l2 = sl[(f0 + f + 2) * 65 + m];
            float l3 = sl[(f0 + f + 3) * 65 + m];
            se += __expf(l0 - mx) + __expf(l1 - mx) + __expf(l2 - mx) + __expf(l3 - mx);
            float e0 = __expf(t4.x), e1 = __expf(t4.y), e2 = __expf(t4.z), e3 = __expf(t4.w);
            W  += e0 * l0 + e1 * l1 + e2 * l2 + e3 * l3;
            Zt += e0 + e1 + e2 + e3;
        }
        float4* hp = (float4*)(smem + SM_HP);
        if (h > 0) hp[h * 64 + m] = make_float4(mx, se, W, Zt);
        __syncthreads();
        if (h == 0) {
#pragma unroll
            for (int hh = 1; hh < 4; hh++) {
                float4 q = hp[hh * 64 + m];
                float nm = fmaxf(mx, q.x);
                se = se * __expf(mx - nm) + q.y * __expf(q.x - nm);
                mx = nm; W += q.z; Zt += q.w;
            }
            g_part[(size_t)m * NBLK_ + blockIdx.x] = make_float4(mx, se, W, Zt);
        }
    }
}

// ---------------------------------------------------------------------------
// Kernel 2: merge 128 partials per batch row -> row loss -> mean (1 block)
// thread (m = tid>>2, qq = tid&3) merges partials qq*32..qq*32+31 of row m
// ---------------------------------------------------------------------------
__global__ void __launch_bounds__(256, 1)
reduce_kernel(float* __restrict__ out) {
    __shared__ float rl[B_];
    const int tid = threadIdx.x;
    const int m  = tid >> 2;
    const int qq = tid & 3;
    float mx = -3.4e38f, se = 0.f, W = 0.f, Zt = 0.f;
    for (int i = 0; i < 32; i++) {
        float4 p = g_part[(size_t)m * NBLK_ + qq * 32 + i];
        float nm = fmaxf(mx, p.x);
        se = se * __expf(mx - nm) + p.y * __expf(p.x - nm);
        mx = nm; W += p.z; Zt += p.w;
    }
#pragma unroll
    for (int off = 1; off < 4; off <<= 1) {
        float omx = __shfl_xor_sync(0xffffffffu, mx, off);
        float ose = __shfl_xor_sync(0xffffffffu, se, off);
        float oW  = __shfl_xor_sync(0xffffffffu, W,  off);
        float oZ  = __shfl_xor_sync(0xffffffffu, Zt, off);
        float nm = fmaxf(mx, omx);
        se = se * __expf(mx - nm) + ose * __expf(omx - nm);
        mx = nm; W += oW; Zt += oZ;
    }
    if (qq == 0) rl[m] = (mx + logf(se)) - W / Zt;
    __syncthreads();
    if (tid < 32) {
        float v = rl[tid] + rl[tid + 32];
#pragma unroll
        for (int off = 16; off; off >>= 1) v += __shfl_xor_sync(0xffffffffu, v, off);
        if (tid == 0) out[0] = v * (1.0f / B_);
    }
}

// ---------------------------------------------------------------------------
extern "C" void kernel_launch(void* const* d_in, const int* in_sizes, int n_in,
                              void* d_out, int out_size) {
    const float* x  = nullptr;
    const float* tg = nullptr;
    const float* ft = nullptr;
    for (int i = 0; i < n_in; i++) {
        if      (in_sizes[i] == B_ * D_) x  = (const float*)d_in[i];
        else if (in_sizes[i] == B_ * N_) tg = (const float*)d_in[i];
        else if (in_sizes[i] == N_ * D_) ft = (const float*)d_in[i];
    }

    cudaFuncSetAttribute(fused_kernel, cudaFuncAttributeMaxDynamicSharedMemorySize,
                         SMEM_TOTAL);

    fused_kernel<<<NBLK_, NTHR, SMEM_TOTAL>>>(x, ft, tg);
    reduce_kernel<<<1, 256>>>((float*)d_out);
}